// round 10
// baseline (speedup 1.0000x reference)
#include <cuda_runtime.h>

#define NCLS 19
#define CH   32
#define IN_H 128
#define IN_W 128
#define OUT_H 512
#define OUT_W 512
#define NB   4
#define HB   16   // histogram blocks per batch
#define GRID_MAIN (NB * 64 * 2)

// Device-global scratch (no allocations allowed in kernel_launch).
__device__ float    g_T[(size_t)NB * IN_H * IN_W * CH];  // transposed embedding (N,H,W,C)
__device__ float    g_S1[NB * NCLS * CH];                // per (n,k,c) sum
__device__ float    g_S2[NB * NCLS * CH];                // per (n,k,c) sum of squares
__device__ int      g_hist[NB][HB][NCLS];                // partial label histograms
__device__ unsigned g_done;

// ---------------------------------------------------------------------------
// Prep: (N,C,H,W)->(N,H,W,C) transpose + zero accumulators + label histogram.
__global__ void __launch_bounds__(1024) prep_kernel(const float* __restrict__ in,
                                                    const int* __restrict__ label) {
    __shared__ float tile[32][33];
    __shared__ int   whist[32][NCLS];

    const int n  = blockIdx.z;          // 4
    const int y  = blockIdx.y;          // 128
    const int xb = blockIdx.x * 32;     // 4 tiles along W
    const int tx = threadIdx.x;
    const int ty = threadIdx.y;
    const int tid = ty * 32 + tx;

    // transpose: read channel ty, x = xb+tx (coalesced)
    tile[ty][tx] = in[((((size_t)n * CH + ty) * IN_H + y) * IN_W) + xb + tx];

    // one block zeroes the global accumulators + done flag
    if (blockIdx.x == 3 && y == 127 && n == 3) {
        for (int i = tid; i < NB * NCLS * CH; i += 1024) { g_S1[i] = 0.f; g_S2[i] = 0.f; }
        if (tid == 0) g_done = 0u;
    }

    // HB blocks per batch build the label histogram (match_any, no atomics)
    if (blockIdx.x == 0 && y < HB) {
        const int w    = tid >> 5;
        const int lane = tid & 31;
        for (int i = lane; i < NCLS; i += 32) whist[w][i] = 0;
        __syncwarp();
        const int4* lp = (const int4*)(label + (size_t)n * OUT_H * OUT_W
                                             + (size_t)y * (OUT_H * OUT_W / HB));
        #pragma unroll
        for (int r = 0; r < 4; ++r) {
            int4 L = lp[r * 1024 + tid];           // coalesced
            int ks[4] = {L.x, L.y, L.z, L.w};
            #pragma unroll
            for (int j = 0; j < 4; ++j) {
                int k = (int)min((unsigned)ks[j], (unsigned)(NCLS - 1));
                unsigned m  = __match_any_sync(0xffffffffu, k);
                int leader  = __ffs(m) - 1;
                if (lane == leader) whist[w][k] += __popc(m);
            }
        }
        __syncthreads();   // block-uniform branch: legal
        if (tid < NCLS) {
            int c = 0;
            #pragma unroll
            for (int ww = 0; ww < 32; ++ww) c += whist[ww][tid];
            g_hist[n][y][tid] = c;
        }
    }

    __syncthreads();
    // write: x = xb+ty, channel tx (coalesced in c)
    g_T[((((size_t)n * IN_H + y) * IN_W) + xb + ty) * CH + tx] = tile[tx][ty];
}

// ---------------------------------------------------------------------------
// Main pass: warp = half an output row (256 px = 64 groups), lane = channel.
// Class bins live in REGISTERS (warp-uniform switch) — zero smem in hot loop.
#define CASE_J(j) case j: a##j += _v; b##j = fmaf(_v, _v, b##j); break;
#define ACCUM(kk, vv) do { float _v = (vv); switch (kk) {                      \
    CASE_J(0)  CASE_J(1)  CASE_J(2)  CASE_J(3)  CASE_J(4)  CASE_J(5)           \
    CASE_J(6)  CASE_J(7)  CASE_J(8)  CASE_J(9)  CASE_J(10) CASE_J(11)          \
    CASE_J(12) CASE_J(13) CASE_J(14) CASE_J(15) CASE_J(16) CASE_J(17)          \
    CASE_J(18) } } while (0)
#define STORE_J(j) sw[j * CH] = make_float2(a##j, b##j);

__global__ void __launch_bounds__(256, 3) main_kernel(const int* __restrict__ label,
                                                      float* __restrict__ out) {
    __shared__ __align__(16) unsigned char raw[8 * NCLS * CH * 8];  // 38912 B staging
    __shared__ __align__(16) int4 slab[8][64];                      // 8192 B labels
    float2 (*s)[NCLS * CH] = reinterpret_cast<float2 (*)[NCLS * CH]>(raw);
    __shared__ unsigned s_last;

    const int tid  = threadIdx.x;
    const int w    = tid >> 5;
    const int lane = tid & 31;
    const int bx   = blockIdx.x;
    const int n    = bx >> 7;            // 4 batches
    const int rem  = bx & 127;
    const int rb   = rem >> 1;           // 64 row-blocks
    const int half = rem & 1;            // left / right half of the row
    const int y    = rb * 8 + w;         // warp's output row
    const int g0   = half * 64;          // first 4-px group of this warp

    // stage this warp's 256 labels into smem (2 coalesced LDG.128 per lane)
    {
        const int4* lp = (const int4*)(label + ((size_t)(n * OUT_H + y) * OUT_W)) + g0;
        slab[w][lane]      = lp[lane];
        slab[w][lane + 32] = lp[lane + 32];
    }
    __syncwarp();   // slab[w] written only by warp w

    // y interpolation (scale exactly 4, half-pixel sampling)
    const int   y0  = ((y + 2) >> 2) - 1;
    const float fy  = 0.125f + 0.25f * (float)((y + 2) & 3);
    const int   y0c = y0 < 0 ? 0 : y0;
    const int   y1c = (y0 + 1) > (IN_H - 1) ? (IN_H - 1) : (y0 + 1);

    const float* pA = g_T + ((size_t)(n * IN_H + y0c) * IN_W + g0) * CH + lane;
    const float* pB = g_T + ((size_t)(n * IN_H + y1c) * IN_W + g0) * CH + lane;

    // 19 register bins per lane: a_k = sum(v), b_k = sum(v^2) for class k
    float a0=0,a1=0,a2=0,a3=0,a4=0,a5=0,a6=0,a7=0,a8=0,a9=0,a10=0,a11=0,
          a12=0,a13=0,a14=0,a15=0,a16=0,a17=0,a18=0;
    float b0=0,b1=0,b2=0,b3=0,b4=0,b5=0,b6=0,b7=0,b8=0,b9=0,b10=0,b11=0,
          b12=0,b13=0,b14=0,b15=0,b16=0,b17=0,b18=0;

    // prologue: yvB = column g0; yvA = column g0-1 (clamped for half 0)
    float ax = pA[0], bx2 = pB[0];
    float yvB = fmaf(fy, bx2 - ax, ax);
    float yvA;
    if (half) {
        float a1r = pA[-CH], b1r = pB[-CH];
        yvA = fmaf(fy, b1r - a1r, a1r);
    } else {
        yvA = yvB;                        // column -1 clamps to column 0
    }
    pA += CH; pB += CH;                   // now at column g0+1 (first yvC)

    // 63 clean groups (rel t = 0..62)
    #pragma unroll 1
    for (int t = 0; t < 63; ++t) {
        float a = pA[0], b = pB[0];
        pA += CH; pB += CH;
        float yvC = fmaf(fy, b - a, a);
        int4  L   = slab[w][t];
        float d0  = yvB - yvA;
        float d1  = yvC - yvB;
        ACCUM(L.x, fmaf(0.625f, d0, yvA));
        ACCUM(L.y, fmaf(0.875f, d0, yvA));
        ACCUM(L.z, fmaf(0.125f, d1, yvB));
        ACCUM(L.w, fmaf(0.375f, d1, yvB));
        yvA = yvB; yvB = yvC;
    }
    {   // final group (rel t = 63): half 0 loads col 64; half 1 clamps col 128
        float yvC;
        if (!half) {
            float a = pA[0], b = pB[0];
            yvC = fmaf(fy, b - a, a);
        } else {
            yvC = yvB;
        }
        int4  L  = slab[w][63];
        float d0 = yvB - yvA;
        float d1 = yvC - yvB;
        ACCUM(L.x, fmaf(0.625f, d0, yvA));
        ACCUM(L.y, fmaf(0.875f, d0, yvA));
        ACCUM(L.z, fmaf(0.125f, d1, yvB));
        ACCUM(L.w, fmaf(0.375f, d1, yvB));
    }

    // stage register bins to smem (every element written — no zero-init needed)
    {
        float2* sw = s[w] + lane;
        STORE_J(0)  STORE_J(1)  STORE_J(2)  STORE_J(3)  STORE_J(4)  STORE_J(5)
        STORE_J(6)  STORE_J(7)  STORE_J(8)  STORE_J(9)  STORE_J(10) STORE_J(11)
        STORE_J(12) STORE_J(13) STORE_J(14) STORE_J(15) STORE_J(16) STORE_J(17)
        STORE_J(18)
    }
    __syncthreads();

    // reduce 8 warp copies -> global atomics
    for (int i = tid; i < NCLS * CH; i += 256) {
        float a = 0.f, b = 0.f;
        #pragma unroll
        for (int ww = 0; ww < 8; ++ww) { float2 v = s[ww][i]; a += v.x; b += v.y; }
        atomicAdd(&g_S1[n * NCLS * CH + i], a);
        atomicAdd(&g_S2[n * NCLS * CH + i], b);
    }

    __threadfence();
    if (tid == 0) s_last = (atomicAdd(&g_done, 1u) == (unsigned)(gridDim.x - 1));
    __syncthreads();
    if (!s_last) return;

    // ---------------- epilogue (last CTA, reuses smem) ----------------
    struct Epi {
        float cnt[NB][NCLS];
        float mu[NB][NCLS][CH];
        float intra[NB][NCLS];
        float interp[NB][2];
        float nfg[NB];
        float l2i[NB];
    };
    Epi* e = reinterpret_cast<Epi*>(raw);
    __syncthreads();

    if (tid < NB * NCLS) {
        int nn = tid / NCLS, k = tid % NCLS;
        int c = 0;
        #pragma unroll
        for (int h = 0; h < HB; ++h) c += g_hist[nn][h][k];
        e->cnt[nn][k] = (float)c;
    }
    __syncthreads();

    {   // per-class mean + intra (warp pair per batch)
        int nn = w >> 1, sub = w & 1;
        for (int k = sub; k < NCLS; k += 2) {
            float cn = e->cnt[nn][k];
            float s1 = __ldcg(&g_S1[nn * NCLS * CH + k * CH + lane]);
            float s2 = __ldcg(&g_S2[nn * NCLS * CH + k * CH + lane]);
            float m  = s1 / (cn + 1.0f);
            e->mu[nn][k][lane] = m;
            float t2 = s2 + m * fmaf(cn, m, -2.0f * s1);
            #pragma unroll
            for (int o = 16; o; o >>= 1) t2 += __shfl_xor_sync(0xffffffffu, t2, o);
            if (lane == 0) e->intra[nn][k] = t2 / ((float)CH * (cn + 1.0f));
        }
    }
    __syncthreads();

    if (tid < NB) {
        float nf = 0.f, li = 0.f;
        for (int k = 1; k < NCLS; ++k)
            if (e->cnt[tid][k] > 0.f) { nf += 1.f; li += e->intra[tid][k]; }
        e->nfg[tid] = nf;
        e->l2i[tid] = li / nf;
    }
    __syncthreads();

    {   // inter: masked pairwise mean-squared distances
        int nn = w >> 1, sub = w & 1;
        float acc = 0.f;
        for (int p = sub; p < NCLS * NCLS; p += 2) {
            int j = p / NCLS, k = p - j * NCLS;
            if (j >= 1 && k >= 1 && e->cnt[nn][j] > 0.f && e->cnt[nn][k] > 0.f) {
                float d = e->mu[nn][j][lane] - e->mu[nn][k][lane];
                acc = fmaf(d, d, acc);
            }
        }
        #pragma unroll
        for (int o = 16; o; o >>= 1) acc += __shfl_xor_sync(0xffffffffu, acc, o);
        if (lane == 0) e->interp[nn][sub] = acc / (float)CH;
    }
    __syncthreads();

    if (tid < NB) {
        float inter = e->interp[tid][0] + e->interp[tid][1];
        out[tid] = e->l2i[tid] - inter / (e->nfg[tid] * e->nfg[tid]);
    }
}

// ---------------------------------------------------------------------------
extern "C" void kernel_launch(void* const* d_in, const int* in_sizes, int n_in,
                              void* d_out, int out_size) {
    const float* emb   = (const float*)d_in[0];   // (4,32,128,128) f32
    const int*   label = (const int*)d_in[1];     // (4,512,512) int32
    float*       out   = (float*)d_out;           // (4,) f32

    prep_kernel<<<dim3(IN_W / 32, IN_H, NB), dim3(32, 32)>>>(emb, label);
    main_kernel<<<GRID_MAIN, 256>>>(label, out);
}

// round 11
// speedup vs baseline: 1.9935x; 1.9935x over previous
#include <cuda_runtime.h>

#define NCLS 19
#define CH   32
#define IN_H 128
#define IN_W 128
#define OUT_H 512
#define OUT_W 512
#define NB   4
#define HB   16
#define TPAD 67   // tile column pad (67%32=3, coprime -> conflict-free)

__device__ float    g_S1[NB * NCLS * CH];
__device__ float    g_S2[NB * NCLS * CH];
__device__ int      g_hist[NB][HB][NCLS];
__device__ unsigned g_done;

// ---------------------------------------------------------------------------
// Histogram + accumulator zeroing (no transpose needed anymore).
__global__ void __launch_bounds__(256) hist_kernel(const int* __restrict__ label) {
    __shared__ int whist[8][NCLS];
    const int n   = blockIdx.x >> 4;
    const int h   = blockIdx.x & 15;
    const int tid = threadIdx.x;
    const int w   = tid >> 5;
    const int lane = tid & 31;

    if (blockIdx.x == 0) {
        for (int i = tid; i < NB * NCLS * CH; i += 256) { g_S1[i] = 0.f; g_S2[i] = 0.f; }
        if (tid == 0) g_done = 0u;
    }

    for (int i = lane; i < NCLS; i += 32) whist[w][i] = 0;
    __syncwarp();

    const int4* lp = (const int4*)(label + (size_t)n * OUT_H * OUT_W
                                         + (size_t)h * (OUT_H * OUT_W / HB));
    #pragma unroll
    for (int r = 0; r < 16; ++r) {
        int4 L = lp[r * 256 + tid];
        int ks[4] = {L.x, L.y, L.z, L.w};
        #pragma unroll
        for (int j = 0; j < 4; ++j) {
            int k = (int)min((unsigned)ks[j], (unsigned)(NCLS - 1));
            unsigned m = __match_any_sync(0xffffffffu, k);
            if (lane == (__ffs(m) - 1)) whist[w][k] += __popc(m);
        }
    }
    __syncthreads();
    if (tid < NCLS) {
        int c = 0;
        #pragma unroll
        for (int ww = 0; ww < 8; ++ww) c += whist[ww][tid];
        g_hist[n][h][tid] = c;
    }
}

// ---------------------------------------------------------------------------
// Main: CTA = 128 threads (4 warps), warp = half of output row y = 4q+w.
// Smem-resident embedding tile + packed labels: hot loop has ZERO global ops.
__global__ void __launch_bounds__(128) main_kernel(const float* __restrict__ emb,
                                                   const int*   __restrict__ label,
                                                   float* __restrict__ out) {
    __shared__ float    tile[3][CH][TPAD];                 // 25728 B
    __shared__ __align__(16) unsigned char raw[4 * NCLS * CH * 8]; // 19456 B bins
    __shared__ unsigned slab[4][64];                       // 1024 B packed labels
    __shared__ unsigned s_last;
    float2 (*s)[NCLS * CH] = reinterpret_cast<float2 (*)[NCLS * CH]>(raw);

    const int tid  = threadIdx.x;
    const int w    = tid >> 5;
    const int lane = tid & 31;
    const int bx   = blockIdx.x;
    const int n    = bx >> 8;            // 4 batches
    const int q    = (bx >> 1) & 127;    // 128 row-quads
    const int half = bx & 1;
    const int y    = 4 * q + w;
    const int g0   = half * 64;          // first input column group

    // ---- stage labels (packed 4x8bit per group word) ----
    {
        const int4* lp = (const int4*)(label + ((size_t)(n * OUT_H + y) * OUT_W)) + g0;
        int4 L0 = lp[lane];
        int4 L1 = lp[lane + 32];
        slab[w][lane]      = (unsigned)L0.x | ((unsigned)L0.y << 8) |
                             ((unsigned)L0.z << 16) | ((unsigned)L0.w << 24);
        slab[w][lane + 32] = (unsigned)L1.x | ((unsigned)L1.y << 8) |
                             ((unsigned)L1.z << 16) | ((unsigned)L1.w << 24);
    }

    // ---- load embedding tile: rows q-1,q,q+1 (clamped), cols g0-1..g0+64 ----
    {
        const float* eb = emb + (size_t)n * CH * IN_H * IN_W;
        for (int idx = tid; idx < 3 * CH * 66; idx += 128) {
            int rr  = idx / (CH * 66);
            int rem = idx - rr * (CH * 66);
            int c   = rem / 66;
            int i   = rem - c * 66;
            int row = q - 1 + rr; row = row < 0 ? 0 : (row > IN_H - 1 ? IN_H - 1 : row);
            int col = g0 - 1 + i; col = col < 0 ? 0 : (col > IN_W - 1 ? IN_W - 1 : col);
            tile[rr][c][i] = __ldg(&eb[((size_t)c * IN_H + row) * IN_W + col]);
        }
    }

    // ---- zero bins ----
    for (int i = tid; i < 4 * NCLS * CH / 2; i += 128)
        ((float4*)raw)[i] = make_float4(0.f, 0.f, 0.f, 0.f);
    __syncthreads();

    // ---- hot loop (pure smem) ----
    const float fy = 0.125f + 0.25f * (float)((y + 2) & 3);
    const int   rA = w >> 1;             // w=0,1 -> rows(0,1); w=2,3 -> rows(1,2)
    const float* tAp = &tile[rA][lane][0];
    const float* tBp = &tile[rA + 1][lane][0];
    float2* __restrict__ sbl = s[w] + lane;

    auto bin = [&](int k, float v) {
        float2* p = sbl + k * CH;
        float2 o = *p;
        o.x += v;
        o.y = fmaf(v, v, o.y);
        *p = o;
    };

    float a0 = tAp[0], b0 = tBp[0];
    float yvA = fmaf(fy, b0 - a0, a0);   // column g0-1 (clamped)
    float a1 = tAp[1], b1 = tBp[1];
    float yvB = fmaf(fy, b1 - a1, a1);   // column g0

    #pragma unroll 4
    for (int t = 0; t < 64; ++t) {
        float a = tAp[t + 2], b = tBp[t + 2];   // column g0+t+1 (clamped at load)
        float yvC = fmaf(fy, b - a, a);
        unsigned Lp = slab[w][t];
        float d0 = yvB - yvA;
        float d1 = yvC - yvB;
        bin((int)(Lp & 0xffu),         fmaf(0.625f, d0, yvA));
        bin((int)((Lp >> 8) & 0xffu),  fmaf(0.875f, d0, yvA));
        bin((int)((Lp >> 16) & 0xffu), fmaf(0.125f, d1, yvB));
        bin((int)(Lp >> 24),           fmaf(0.375f, d1, yvB));
        yvA = yvB; yvB = yvC;
    }
    __syncthreads();

    // ---- reduce 4 warp copies -> global atomics ----
    for (int i = tid; i < NCLS * CH; i += 128) {
        float a = 0.f, b = 0.f;
        #pragma unroll
        for (int ww = 0; ww < 4; ++ww) { float2 v = s[ww][i]; a += v.x; b += v.y; }
        atomicAdd(&g_S1[n * NCLS * CH + i], a);
        atomicAdd(&g_S2[n * NCLS * CH + i], b);
    }

    __threadfence();
    if (tid == 0) s_last = (atomicAdd(&g_done, 1u) == (unsigned)(gridDim.x - 1));
    __syncthreads();
    if (!s_last) return;

    // ---------------- epilogue (last CTA, reuses bin smem) ----------------
    struct Epi {
        float cnt[NB][NCLS];
        float mu[NB][NCLS][CH];
        float intra[NB][NCLS];
        float inter[NB];
        float nfg[NB];
        float l2i[NB];
    };
    Epi* e = reinterpret_cast<Epi*>(raw);
    __syncthreads();

    if (tid < NB * NCLS) {
        int nn = tid / NCLS, k = tid % NCLS;
        int c = 0;
        #pragma unroll
        for (int h = 0; h < HB; ++h) c += g_hist[nn][h][k];
        e->cnt[nn][k] = (float)c;
    }
    __syncthreads();

    {   // warp w = batch w: per-class mean + intra
        for (int k = 0; k < NCLS; ++k) {
            float cn = e->cnt[w][k];
            float s1 = __ldcg(&g_S1[w * NCLS * CH + k * CH + lane]);
            float s2 = __ldcg(&g_S2[w * NCLS * CH + k * CH + lane]);
            float m  = s1 / (cn + 1.0f);
            e->mu[w][k][lane] = m;
            float t2 = s2 + m * fmaf(cn, m, -2.0f * s1);
            #pragma unroll
            for (int o = 16; o; o >>= 1) t2 += __shfl_xor_sync(0xffffffffu, t2, o);
            if (lane == 0) e->intra[w][k] = t2 / ((float)CH * (cn + 1.0f));
        }
    }
    __syncthreads();

    if (tid < NB) {
        float nf = 0.f, li = 0.f;
        for (int k = 1; k < NCLS; ++k)
            if (e->cnt[tid][k] > 0.f) { nf += 1.f; li += e->intra[tid][k]; }
        e->nfg[tid] = nf;
        e->l2i[tid] = li / nf;
    }
    __syncthreads();

    {   // warp w = batch w: inter-class pairwise distances
        float acc = 0.f;
        for (int j = 1; j < NCLS; ++j) {
            if (e->cnt[w][j] <= 0.f) continue;
            float mj = e->mu[w][j][lane];
            for (int k = 1; k < NCLS; ++k) {
                if (e->cnt[w][k] > 0.f) {
                    float d = mj - e->mu[w][k][lane];
                    acc = fmaf(d, d, acc);
                }
            }
        }
        #pragma unroll
        for (int o = 16; o; o >>= 1) acc += __shfl_xor_sync(0xffffffffu, acc, o);
        if (lane == 0) e->inter[w] = acc / (float)CH;
    }
    __syncthreads();

    if (tid < NB)
        out[tid] = e->l2i[tid] - e->inter[tid] / (e->nfg[tid] * e->nfg[tid]);
}

// ---------------------------------------------------------------------------
extern "C" void kernel_launch(void* const* d_in, const int* in_sizes, int n_in,
                              void* d_out, int out_size) {
    const float* emb   = (const float*)d_in[0];   // (4,32,128,128) f32
    const int*   label = (const int*)d_in[1];     // (4,512,512) int32
    float*       out   = (float*)d_out;           // (4,) f32

    hist_kernel<<<NB * HB, 256>>>(label);
    main_kernel<<<NB * 128 * 2, 128>>>(emb, label, out);
}